// round 11
// baseline (speedup 1.0000x reference)
#include <cuda_runtime.h>
#include <cstdint>

#define B_ 4
#define L_ 512
#define D_ 256
#define U_ 64
#define TI 8
#define TJ 32

// scratch (static __device__ globals -- no allocation)
__device__ float g_q[B_*L_*U_];
__device__ float g_k[B_*L_*U_];
// flash-decoding partials: [b][it][seg][row][264] (acc 0..255, m @256, s @257)
__device__ float g_part[4][64][4][8][264];

__device__ __forceinline__ float tanh_ap(float x){ float y; asm("tanh.approx.f32 %0, %1;" : "=f"(y) : "f"(x)); return y; }
__device__ __forceinline__ float ex2_ap(float x){ float y; asm("ex2.approx.f32 %0, %1;" : "=f"(y) : "f"(x)); return y; }
__device__ __forceinline__ unsigned long long dup2(float x){
    unsigned long long r; asm("mov.b64 %0, {%1, %1};" : "=l"(r) : "f"(x)); return r;
}
__device__ __forceinline__ void fma2(unsigned long long &a, unsigned long long x, unsigned long long y){
    asm("fma.rn.f32x2 %0, %1, %2, %0;" : "+l"(a) : "l"(x), "l"(y));
}
__device__ __forceinline__ void mul2(unsigned long long &a, unsigned long long x){
    asm("mul.rn.f32x2 %0, %0, %1;" : "+l"(a) : "l"(x));
}
__device__ __forceinline__ float2 unpack2(unsigned long long v){
    float lo, hi; asm("mov.b64 {%0, %1}, %2;" : "=f"(lo), "=f"(hi) : "l"(v)); return make_float2(lo, hi);
}
__device__ __forceinline__ unsigned smem_u32(const void* p){
    return (unsigned)__cvta_generic_to_shared(p);
}
__device__ __forceinline__ void cp16(unsigned dst, const void* src){
    asm volatile("cp.async.cg.shared.global [%0], [%1], 16;" :: "r"(dst), "l"(src));
}
__device__ __forceinline__ void cp_commit(){ asm volatile("cp.async.commit_group;"); }
__device__ __forceinline__ void cp_wait0(){ asm volatile("cp.async.wait_group 0;"); }
__device__ __forceinline__ void cp_wait1(){ asm volatile("cp.async.wait_group 1;"); }
__device__ __forceinline__ void cp_wait2(){ asm volatile("cp.async.wait_group 2;"); }

// ---------------------------------------------------------------------------
// Phase 1: q = X@Wt ; k = X@Wx + bh.  128 blocks x 256 threads, 32 rows/block.
// (unchanged from R10 -- measured improvement)
// ---------------------------------------------------------------------------
__global__ void __launch_bounds__(256) proj_kernel(
    const float* __restrict__ X, const float* __restrict__ Wt,
    const float* __restrict__ Wx, const float* __restrict__ bh)
{
    extern __shared__ __align__(16) float psm[];
    float* W_s = psm;            // 64KB
    float* x_s = psm + 16384;    // 32KB

    const int bid  = blockIdx.x;
    const bool is_k = bid >= 64;
    const int rb   = bid & 63;
    const float* __restrict__ W = is_k ? Wx : Wt;
    const int t    = threadIdx.x;
    const int row0 = rb * 32;

    const float4* W4 = reinterpret_cast<const float4*>(W);
    const float4* X4 = reinterpret_cast<const float4*>(X) + row0*(D_/4);
    for (int i = t; i < (D_*U_)/4; i += 256) reinterpret_cast<float4*>(W_s)[i] = W4[i];
    for (int i = t; i < (32*D_)/4;  i += 256) reinterpret_cast<float4*>(x_s)[i] = X4[i];
    __syncthreads();

    const int quad = t & 15;
    const int r    = t >> 4;
    const float4* xa4 = reinterpret_cast<const float4*>(x_s) + r*(D_/4);
    const float4* xb4 = reinterpret_cast<const float4*>(x_s) + (r+16)*(D_/4);

    unsigned long long a01_0 = 0ull, a23_0 = 0ull;
    unsigned long long a01_1 = 0ull, a23_1 = 0ull;

    #pragma unroll 2
    for (int d4 = 0; d4 < D_/4; ++d4) {
        float4 xa = xa4[d4];
        float4 xb = xb4[d4];
        const float* xaf = reinterpret_cast<const float*>(&xa);
        const float* xbf = reinterpret_cast<const float*>(&xb);
        #pragma unroll
        for (int c = 0; c < 4; ++c) {
            ulonglong2 w2 = *reinterpret_cast<const ulonglong2*>(W_s + (d4*4+c)*U_ + quad*4);
            unsigned long long xx0 = dup2(xaf[c]);
            unsigned long long xx1 = dup2(xbf[c]);
            fma2(a01_0, xx0, w2.x);
            fma2(a23_0, xx0, w2.y);
            fma2(a01_1, xx1, w2.x);
            fma2(a23_1, xx1, w2.y);
        }
    }

    float bx = 0.f, by = 0.f, bz = 0.f, bw = 0.f;
    if (is_k) { bx = bh[quad*4+0]; by = bh[quad*4+1]; bz = bh[quad*4+2]; bw = bh[quad*4+3]; }

    float* base = (is_k ? g_k : g_q);
    {
        float2 v01 = unpack2(a01_0), v23 = unpack2(a23_0);
        float4 o; o.x = v01.x+bx; o.y = v01.y+by; o.z = v23.x+bz; o.w = v23.y+bw;
        *reinterpret_cast<float4*>(base + (row0 + r)*U_ + quad*4) = o;
    }
    {
        float2 v01 = unpack2(a01_1), v23 = unpack2(a23_1);
        float4 o; o.x = v01.x+bx; o.y = v01.y+by; o.z = v23.x+bz; o.w = v23.y+bw;
        *reinterpret_cast<float4*>(base + (row0 + r + 16)*U_ + quad*4) = o;
    }
}

// ---------------------------------------------------------------------------
// Phase 2a: flash-decoding partials. 640 CTAs x 256 threads, 3 CTAs/SM.
// CTA = (batch b, row-tile it, segment s of <=4 j-tiles).
// it<16 (single segment) writes output directly; else flushes (m,s,acc).
// k double-buffered cp.async; X single-buffered, fill hidden under score via
// wait_group(2)->(1) choreography. Sum-shuffle overlapped with PV.
// smem: kbuf 16K | Xs 32K | q 2K | wa 256 | p2(dup) 2K | alpha 32 | pm/ps 64
// ---------------------------------------------------------------------------
__global__ void __launch_bounds__(256, 3) attn_partial(
    const float* __restrict__ X, const float* __restrict__ Wa,
    float* __restrict__ out)
{
    extern __shared__ __align__(16) unsigned char smem_raw[];
    float4* kbuf   = reinterpret_cast<float4*>(smem_raw);                   // 16KB (2 bufs)
    float*  Xs     = reinterpret_cast<float*>(smem_raw + 16384);            // 32KB
    float4* q_s    = reinterpret_cast<float4*>(smem_raw + 16384 + 32768);   // 2KB
    float4* wa4    = reinterpret_cast<float4*>(smem_raw + 51200);           // 256B
    float2* p2     = reinterpret_cast<float2*>(smem_raw + 51456);           // 2KB (dup pairs)
    float*  alpha_s= reinterpret_cast<float*>(smem_raw + 53504);            // 32B
    float*  pm     = reinterpret_cast<float*>(smem_raw + 53536);            // 32B
    float*  ps     = reinterpret_cast<float*>(smem_raw + 53568);            // 32B

    const int t    = threadIdx.x;
    const int lane = t & 31;
    const int w    = t >> 5;                 // warp = row 0..7

    // decode CTA -> (b, it, s); LPT: large row-tiles (most segments) first
    const int b   = blockIdx.x & 3;
    const int sid = 159 - (blockIdx.x >> 2);
    int it, s;
    if      (sid < 16) { it = sid;                 s = 0; }
    else if (sid < 48) { it = 16 + (sid-16)/2;     s = (sid-16)%2; }
    else if (sid < 96) { it = 32 + (sid-48)/3;     s = (sid-48)%3; }
    else               { it = 48 + (sid-96)/4;     s = (sid-96)%4; }

    const int i0   = it * TI;
    const int ntj  = it/4 + 1;
    const int t0   = s*4;
    const int t1   = (t0 + 4 < ntj) ? (t0 + 4) : ntj;
    const bool single = (it < 16);           // one segment -> direct output

    const float* __restrict__ Xb = X   + b*L_*D_;
    const float* __restrict__ kb = g_k + b*L_*U_;
    const float* __restrict__ qb = g_q + b*L_*U_;

    if (t < U_) reinterpret_cast<float*>(wa4)[t] = Wa[t] * 1.4426950408889634f;
    if (t < 128) {
        int i = t >> 4, uq = t & 15;
        q_s[uq*8 + i] = *reinterpret_cast<const float4*>(qb + (i0+i)*U_ + uq*4);
    }

    // cp.async targets
    const int kf_uq0 = t & 15,        kf_j0 = t >> 4;
    const int kf_uq1 = (t+256) & 15,  kf_j1 = (t+256) >> 4;
    const unsigned k_dst0 = smem_u32(kbuf) + (kf_uq0*TJ + kf_j0)*16;
    const unsigned k_dst1 = smem_u32(kbuf) + (kf_uq1*TJ + kf_j1)*16;
    const unsigned x_dst0 = smem_u32(Xs) + t*16;
    const unsigned KBUF_B = 512*16;

    // prologue: commit k(t0) into buffer (t0&1)
    {
        const int j0p = t0*TJ;
        const unsigned off = (t0 & 1)*KBUF_B;
        cp16(k_dst0 + off, kb + (j0p + kf_j0)*U_ + kf_uq0*4);
        cp16(k_dst1 + off, kb + (j0p + kf_j1)*U_ + kf_uq1*4);
        cp_commit();
    }

    float m_run = -1e30f, s_run = 0.f;
    unsigned long long a0l = 0ull, a0h = 0ull, a1l = 0ull, a1h = 0ull;
    const int gi = i0 + w;

    const int dq = t & 63;             // d-quad
    const int rp = t >> 6;             // row pair
    const int lr0 = 2*rp, lr1 = 2*rp + 1;

    for (int n = t0; n < t1; ++n) {
        const int j0  = n * TJ;
        const int cur = n & 1;
        const bool more = (n + 1 < t1);

        __syncthreads();   // prev PV done with Xs/p2 (first iter: orders q/wa stores)

        // commit X(n) fill
        #pragma unroll
        for (int rep = 0; rep < 8; ++rep) {
            int idx = t + rep*256;
            cp16(x_dst0 + rep*4096, Xb + (j0 + (idx>>6))*D_ + (idx&63)*4);
        }
        cp_commit();
        // commit k(n+1) fill
        if (more) {
            const int j0n = j0 + TJ;
            const unsigned off = ((n+1) & 1)*KBUF_B;
            cp16(k_dst0 + off, kb + (j0n + kf_j0)*U_ + kf_uq0*4);
            cp16(k_dst1 + off, kb + (j0n + kf_j1)*U_ + kf_uq1*4);
            cp_commit();
        }
        if (more) cp_wait2(); else cp_wait1();   // k(n) landed
        __syncthreads();                         // k(n) visible CTA-wide

        // ---- score: e[gi][j0+lane] in log2 domain ----
        const float4* kc = kbuf + cur*512;
        float e0 = 0.f, e1 = 0.f;
        #pragma unroll
        for (int uq = 0; uq < 16; ++uq) {
            float4 kv = kc[uq*TJ + lane];    // conflict-free
            float4 qv = q_s[uq*8 + w];       // broadcast
            float4 wa = wa4[uq];             // broadcast
            e0 += wa.x * tanh_ap(qv.x + kv.x);
            e1 += wa.y * tanh_ap(qv.y + kv.y);
            e0 += wa.z * tanh_ap(qv.z + kv.z);
            e1 += wa.w * tanh_ap(qv.w + kv.w);
        }
        float e = e0 + e1;
        if (j0 + lane > gi) e = -1e30f;      // causal: exp2 -> exact 0

        // ---- max + p (sum deferred past barrier) ----
        float mt = e;
        #pragma unroll
        for (int off = 16; off; off >>= 1)
            mt = fmaxf(mt, __shfl_xor_sync(0xffffffffu, mt, off));
        float m_new = fmaxf(m_run, mt);
        float p     = ex2_ap(e - m_new);
        float alpha = ex2_ap(m_run - m_new);
        p2[w*TJ + lane] = make_float2(p, p);     // pre-duplicated (STS.64)
        if (lane == 0) alpha_s[w] = alpha;

        if (more) cp_wait1(); else cp_wait0();   // X(n) landed (k(n+1) may pend)
        __syncthreads();                         // X + p2 + alpha visible

        // sum reduction overlaps PV below
        float st = p;
        #pragma unroll
        for (int off = 16; off; off >>= 1)
            st += __shfl_xor_sync(0xffffffffu, st, off);
        s_run = s_run * alpha + st;
        m_run = m_new;

        // ---- PV: 4 d x 2 rows per thread, packed f32x2 ----
        {
            unsigned long long al0 = dup2(alpha_s[lr0]);
            unsigned long long al1 = dup2(alpha_s[lr1]);
            mul2(a0l, al0); mul2(a0h, al0);
            mul2(a1l, al1); mul2(a1h, al1);
        }
        const ulonglong2* X2 = reinterpret_cast<const ulonglong2*>(Xs);
        const unsigned long long* p0d = reinterpret_cast<const unsigned long long*>(&p2[lr0*TJ]);
        const unsigned long long* p1d = reinterpret_cast<const unsigned long long*>(&p2[lr1*TJ]);
        #pragma unroll
        for (int jc = 0; jc < TJ/4; ++jc) {
            #pragma unroll
            for (int j = 0; j < 4; ++j) {
                ulonglong2 xv = X2[(jc*4 + j)*(D_/4) + dq];   // packed (xlo,xhi)
                unsigned long long d0 = p0d[jc*4 + j];        // broadcast dup pair
                unsigned long long d1 = p1d[jc*4 + j];
                fma2(a0l, xv.x, d0); fma2(a0h, xv.y, d0);
                fma2(a1l, xv.x, d1); fma2(a1h, xv.y, d1);
            }
        }
    }

    // ---- epilogue ----
    if (lane == 0) { pm[w] = m_run; ps[w] = s_run; }
    __syncthreads();

    if (single) {
        const float is0 = 1.0f / ps[lr0];
        const float is1 = 1.0f / ps[lr1];
        float2 vl = unpack2(a0l), vh = unpack2(a0h);
        float4 o0; o0.x = vl.x*is0; o0.y = vl.y*is0; o0.z = vh.x*is0; o0.w = vh.y*is0;
        *reinterpret_cast<float4*>(out + (b*L_ + i0 + lr0)*D_ + dq*4) = o0;
        vl = unpack2(a1l); vh = unpack2(a1h);
        float4 o1; o1.x = vl.x*is1; o1.y = vl.y*is1; o1.z = vh.x*is1; o1.w = vh.y*is1;
        *reinterpret_cast<float4*>(out + (b*L_ + i0 + lr1)*D_ + dq*4) = o1;
    } else {
        float* dst0 = &g_part[b][it][s][lr0][0];
        float* dst1 = &g_part[b][it][s][lr1][0];
        float2 vl = unpack2(a0l), vh = unpack2(a0h);
        float4 f0; f0.x = vl.x; f0.y = vl.y; f0.z = vh.x; f0.w = vh.y;
        *reinterpret_cast<float4*>(dst0 + dq*4) = f0;
        vl = unpack2(a1l); vh = unpack2(a1h);
        float4 f1; f1.x = vl.x; f1.y = vl.y; f1.z = vh.x; f1.w = vh.y;
        *reinterpret_cast<float4*>(dst1 + dq*4) = f1;
        if (t < 8) {
            g_part[b][it][s][t][256] = pm[t];
            g_part[b][it][s][t][257] = ps[t];
        }
    }
}

// ---------------------------------------------------------------------------
// Phase 2b: merge partials for row-tiles with >=2 segments (it >= 16).
// 192 CTAs x 256 threads; thread -> (row t>>5, 8 d's).
// ---------------------------------------------------------------------------
__global__ void __launch_bounds__(256) merge_kernel(float* __restrict__ out)
{
    const int b  = blockIdx.x & 3;
    const int it = 16 + (blockIdx.x >> 2);
    const int nseg = it/16 + 1;              // 2..4
    const int t  = threadIdx.x;
    const int r  = t >> 5;
    const int c  = t & 31;                   // d block: d = c*8 .. +7

    float m[4], sv[4];
    float M = -1e30f;
    for (int k = 0; k < nseg; ++k) {
        m[k]  = g_part[b][it][k][r][256];
        sv[k] = g_part[b][it][k][r][257];
        M = fmaxf(M, m[k]);
    }
    float den = 0.f, wgt[4];
    for (int k = 0; k < nseg; ++k) {
        wgt[k] = ex2_ap(m[k] - M);
        den += wgt[k]*sv[k];
    }
    const float dn = 1.0f / den;

    float4 o0 = make_float4(0,0,0,0), o1 = make_float4(0,0,0,0);
    for (int k = 0; k < nseg; ++k) {
        const float4* a = reinterpret_cast<const float4*>(&g_part[b][it][k][r][0]) + c*2;
        float4 c0 = a[0], c1 = a[1];
        float wk = wgt[k];
        o0.x += wk*c0.x; o0.y += wk*c0.y; o0.z += wk*c0.z; o0.w += wk*c0.w;
        o1.x += wk*c1.x; o1.y += wk*c1.y; o1.z += wk*c1.z; o1.w += wk*c1.w;
    }
    o0.x *= dn; o0.y *= dn; o0.z *= dn; o0.w *= dn;
    o1.x *= dn; o1.y *= dn; o1.z *= dn; o1.w *= dn;
    float4* dst = reinterpret_cast<float4*>(out + (b*L_ + it*TI + r)*D_ + c*8);
    dst[0] = o0; dst[1] = o1;
}

// ---------------------------------------------------------------------------
extern "C" void kernel_launch(void* const* d_in, const int* in_sizes, int n_in,
                              void* d_out, int out_size)
{
    const float* X  = (const float*)d_in[0];
    const float* Wt = (const float*)d_in[1];
    const float* Wx = (const float*)d_in[2];
    const float* bh = (const float*)d_in[3];
    const float* Wa = (const float*)d_in[4];
    // d_in[5] = ba : constant shift inside softmax -> mathematically a no-op

    const int proj_smem = (16384 + 8192) * 4;   // 96KB
    const int part_smem = 53600;                // ~52.3KB -> 3 CTAs/SM
    cudaFuncSetAttribute(proj_kernel,  cudaFuncAttributeMaxDynamicSharedMemorySize, proj_smem);
    cudaFuncSetAttribute(attn_partial, cudaFuncAttributeMaxDynamicSharedMemorySize, part_smem);

    proj_kernel<<<128, 256, proj_smem>>>(X, Wt, Wx, bh);
    attn_partial<<<640, 256, part_smem>>>(X, Wa, (float*)d_out);
    merge_kernel<<<192, 256>>>((float*)d_out);
}